// round 2
// baseline (speedup 1.0000x reference)
#include <cuda_runtime.h>
#include <stdint.h>

#define IN_F  256
#define OUT_F 64
#define MAX_NODES 100000

// Scratch for projected features h = x @ W  (25.6 MB)
__device__ float g_h[(size_t)MAX_NODES * OUT_F];
// 1 if index arrays are int64, 0 if int32 (set by detect_kernel each launch)
__device__ int g_is64;

// ---------------------------------------------------------------------------
// Detect index dtype: int64 values < 2^31 have all-zero high 32-bit words.
// Sample 2048 odd words; for int32 these are random node ids (P(all zero)~0).
// ---------------------------------------------------------------------------
__global__ void detect_kernel(const unsigned int* __restrict__ idx32, int n_elems) {
    int lane = threadIdx.x;
    unsigned int acc = 0;
    int nsamp = 2048;
    if (n_elems < 4096) nsamp = n_elems / 2;
    for (int i = lane; i < nsamp; i += 32) {
        acc |= idx32[2 * i + 1];
    }
    unsigned int any = __ballot_sync(0xffffffffu, acc != 0u);
    if (lane == 0) g_is64 = (any == 0u) ? 1 : 0;
}

// ---------------------------------------------------------------------------
// GEMM: h[n][o] = sum_k x[n][k] * W[k][o].
// W staged in static smem in TWO passes of 128 K-rows (32 KB each) — avoids
// any cudaFuncSetAttribute / dynamic-smem opt-in inside kernel_launch.
// One warp computes 4 nodes; lane owns output cols {lane, lane+32}.
// ---------------------------------------------------------------------------
__global__ void gemm_kernel(const float* __restrict__ x,
                            const float* __restrict__ w,
                            int n_nodes) {
    __shared__ float ws[128 * OUT_F];       // 32 KB

    int warp = threadIdx.x >> 5;
    int lane = threadIdx.x & 31;
    int node0 = (blockIdx.x * 8 + warp) * 4;

    int nvalid = n_nodes - node0;
    if (nvalid > 4) nvalid = 4;

    float acc[4][2];
#pragma unroll
    for (int i = 0; i < 4; i++) { acc[i][0] = 0.f; acc[i][1] = 0.f; }

    for (int pass = 0; pass < 2; pass++) {
        // stage W[pass*128 .. pass*128+127][:] into smem
        {
            const float4* w4 = (const float4*)(w + (size_t)pass * 128 * OUT_F);
            float4* ws4 = (float4*)ws;
            __syncthreads();                 // protect previous pass's reads
            for (int i = threadIdx.x; i < 128 * OUT_F / 4; i += blockDim.x)
                ws4[i] = w4[i];
            __syncthreads();
        }
        if (nvalid <= 0) continue;

        const int kbase = pass * 128;        // in floats
        const float4* xr = (const float4*)(x + (size_t)node0 * IN_F + kbase);
        // row stride in float4s = IN_F/4 = 64

        if (nvalid == 4) {
#pragma unroll 4
            for (int k4 = 0; k4 < 128 / 4; k4++) {
                float4 xv0 = xr[k4];
                float4 xv1 = xr[64 + k4];
                float4 xv2 = xr[128 + k4];
                float4 xv3 = xr[192 + k4];
                const float* f0 = (const float*)&xv0;
                const float* f1 = (const float*)&xv1;
                const float* f2 = (const float*)&xv2;
                const float* f3 = (const float*)&xv3;
#pragma unroll
                for (int kk = 0; kk < 4; kk++) {
                    float w0 = ws[(k4 * 4 + kk) * OUT_F + lane];
                    float w1 = ws[(k4 * 4 + kk) * OUT_F + 32 + lane];
                    acc[0][0] = fmaf(f0[kk], w0, acc[0][0]);
                    acc[0][1] = fmaf(f0[kk], w1, acc[0][1]);
                    acc[1][0] = fmaf(f1[kk], w0, acc[1][0]);
                    acc[1][1] = fmaf(f1[kk], w1, acc[1][1]);
                    acc[2][0] = fmaf(f2[kk], w0, acc[2][0]);
                    acc[2][1] = fmaf(f2[kk], w1, acc[2][1]);
                    acc[3][0] = fmaf(f3[kk], w0, acc[3][0]);
                    acc[3][1] = fmaf(f3[kk], w1, acc[3][1]);
                }
            }
        } else {
            for (int i = 0; i < nvalid; i++) {
                const float* xrow = x + (size_t)(node0 + i) * IN_F + kbase;
                for (int k = 0; k < 128; k++) {
                    float xv = xrow[k];
                    acc[i][0] = fmaf(xv, ws[k * OUT_F + lane], acc[i][0]);
                    acc[i][1] = fmaf(xv, ws[k * OUT_F + 32 + lane], acc[i][1]);
                }
            }
        }
    }

#pragma unroll
    for (int i = 0; i < 4; i++) {
        if (i < nvalid) {
            g_h[(size_t)(node0 + i) * OUT_F + lane]      = acc[i][0];
            g_h[(size_t)(node0 + i) * OUT_F + 32 + lane] = acc[i][1];
        }
    }
}

// ---------------------------------------------------------------------------
// Init output to per-column bias (so edge atomics accumulate on top of it).
// ---------------------------------------------------------------------------
__global__ void init_kernel(float4* __restrict__ out4,
                            const float4* __restrict__ bias4, int total4) {
    int i = blockIdx.x * blockDim.x + threadIdx.x;
    if (i < total4) out4[i] = bias4[i & 15];   // OUT_F/4 = 16 float4 per row
}

// ---------------------------------------------------------------------------
// Edge scatter: 16 threads per edge, one float4 chunk each.
// out[dst] += h[src] * w  via no-return vector reduction (red.global.add.v4).
// ---------------------------------------------------------------------------
__device__ __forceinline__ void red_add_v4(float4* addr, float4 v) {
    asm volatile("red.global.add.v4.f32 [%0], {%1, %2, %3, %4};"
                 :: "l"(addr), "f"(v.x), "f"(v.y), "f"(v.z), "f"(v.w)
                 : "memory");
}

__global__ void edge_kernel(const unsigned int* __restrict__ src32,
                            const unsigned int* __restrict__ dst32,
                            const float* __restrict__ ew,
                            float4* __restrict__ out4,
                            int n_edges) {
    long long tid = (long long)blockIdx.x * blockDim.x + threadIdx.x;
    int e = (int)(tid >> 4);
    int c = (int)(tid & 15);
    if (e >= n_edges) return;

    int is64 = g_is64;
    unsigned int s, d;
    if (is64) { s = src32[2 * (size_t)e]; d = dst32[2 * (size_t)e]; }
    else      { s = src32[e];             d = dst32[e]; }

    float w = __ldg(&ew[e]);
    const float4* h4 = (const float4*)g_h;
    float4 v = h4[(size_t)s * 16 + c];
    float4 r = make_float4(v.x * w, v.y * w, v.z * w, v.w * w);
    red_add_v4(&out4[(size_t)d * 16 + c], r);
}

// ---------------------------------------------------------------------------
// Final ReLU sweep.
// ---------------------------------------------------------------------------
__global__ void relu_kernel(float4* __restrict__ out4, int total4) {
    int i = blockIdx.x * blockDim.x + threadIdx.x;
    if (i < total4) {
        float4 v = out4[i];
        v.x = fmaxf(v.x, 0.f);
        v.y = fmaxf(v.y, 0.f);
        v.z = fmaxf(v.z, 0.f);
        v.w = fmaxf(v.w, 0.f);
        out4[i] = v;
    }
}

// ---------------------------------------------------------------------------
extern "C" void kernel_launch(void* const* d_in, const int* in_sizes, int n_in,
                              void* d_out, int out_size) {
    const float*        x    = (const float*)d_in[0];
    const unsigned int* src  = (const unsigned int*)d_in[1];
    const unsigned int* dst  = (const unsigned int*)d_in[2];
    const float*        ew   = (const float*)d_in[3];
    const float*        w    = (const float*)d_in[4];
    const float*        bias = (const float*)d_in[5];
    float*              out  = (float*)d_out;

    int n_nodes = in_sizes[0] / IN_F;
    int n_edges = in_sizes[3];          // edge_weight count (dtype-independent)
    int total4  = n_nodes * (OUT_F / 4);

    // 0) index dtype detection
    detect_kernel<<<1, 32>>>(src, n_edges);

    // 1) h = x @ W
    int gemm_blocks = (n_nodes + 31) / 32;          // 8 warps * 4 nodes per block
    gemm_kernel<<<gemm_blocks, 256>>>(x, w, n_nodes);

    // 2) out = bias (broadcast)
    init_kernel<<<(total4 + 255) / 256, 256>>>((float4*)out, (const float4*)bias, total4);

    // 3) out[dst] += h[src] * ew
    long long work = (long long)n_edges * 16;
    int edge_blocks = (int)((work + 255) / 256);
    edge_kernel<<<edge_blocks, 256>>>(src, dst, ew, (float4*)out, n_edges);

    // 4) relu
    relu_kernel<<<(total4 + 255) / 256, 256>>>((float4*)out, total4);
}

// round 3
// speedup vs baseline: 1.1369x; 1.1369x over previous
#include <cuda_runtime.h>
#include <stdint.h>

#define IN_F  256
#define OUT_F 64
#define MAX_NODES 100000

// Scratch for projected features h = x @ W  (25.6 MB)
__device__ float g_h[(size_t)MAX_NODES * OUT_F];
// 1 if index arrays are int64, 0 if int32 (set by detect_kernel each launch)
__device__ int g_is64;

// ---------------------------------------------------------------------------
// Detect index dtype: int64 values < 2^31 have all-zero high 32-bit words.
// ---------------------------------------------------------------------------
__global__ void detect_kernel(const unsigned int* __restrict__ idx32, int n_elems) {
    int lane = threadIdx.x;
    unsigned int acc = 0;
    int nsamp = 2048;
    if (n_elems < 4096) nsamp = n_elems / 2;
    for (int i = lane; i < nsamp; i += 32) {
        acc |= idx32[2 * i + 1];
    }
    unsigned int any = __ballot_sync(0xffffffffu, acc != 0u);
    if (lane == 0) g_is64 = (any == 0u) ? 1 : 0;
}

// ---------------------------------------------------------------------------
// GEMM v2: h[n][o] = sum_k x[n][k] * W[k][o].
// Warp computes 8 nodes; lane owns cols {lane, lane+32}. W staged in smem in
// two 128-row passes (32 KB static). Per k-quad: 8 uniform LDG.128 (one per
// node, broadcast across lanes) + 8 LDS + 64 FMA. Bounded register footprint.
// ---------------------------------------------------------------------------
__global__ void gemm_kernel(const float* __restrict__ x,
                            const float* __restrict__ w,
                            int n_nodes) {
    __shared__ float ws[128 * OUT_F];       // 32 KB

    const int warp = threadIdx.x >> 5;
    const int lane = threadIdx.x & 31;
    const int node0 = (blockIdx.x * 8 + warp) * 8;   // 64 nodes per block

    float acc[8][2];
#pragma unroll
    for (int i = 0; i < 8; i++) { acc[i][0] = 0.f; acc[i][1] = 0.f; }

    for (int pass = 0; pass < 2; pass++) {
        __syncthreads();                     // protect previous pass's reads
        {
            const float4* w4 = (const float4*)(w + (size_t)pass * 128 * OUT_F);
            float4* ws4 = (float4*)ws;
            for (int i = threadIdx.x; i < 128 * OUT_F / 4; i += blockDim.x)
                ws4[i] = w4[i];
        }
        __syncthreads();

        if (node0 >= n_nodes) continue;      // keep barrier participation

        const int kbase = pass * 128;

        if (node0 + 8 <= n_nodes) {
            // full 8-node fast path
            const float4* xr = (const float4*)(x + (size_t)node0 * IN_F + kbase);
            // node row stride in float4 = IN_F/4 = 64
            for (int k4 = 0; k4 < 32; k4++) {
                float4 xv[8];
#pragma unroll
                for (int i = 0; i < 8; i++)
                    xv[i] = xr[i * 64 + k4];
#pragma unroll
                for (int kk = 0; kk < 4; kk++) {
                    float w0 = ws[(k4 * 4 + kk) * OUT_F + lane];
                    float w1 = ws[(k4 * 4 + kk) * OUT_F + 32 + lane];
#pragma unroll
                    for (int i = 0; i < 8; i++) {
                        float xs = (kk == 0) ? xv[i].x :
                                   (kk == 1) ? xv[i].y :
                                   (kk == 2) ? xv[i].z : xv[i].w;
                        acc[i][0] = fmaf(xs, w0, acc[i][0]);
                        acc[i][1] = fmaf(xs, w1, acc[i][1]);
                    }
                }
            }
        } else {
            // tail: per-node scalar loop
            int nvalid = n_nodes - node0;
            for (int i = 0; i < nvalid; i++) {
                const float* xrow = x + (size_t)(node0 + i) * IN_F + kbase;
                for (int k = 0; k < 128; k++) {
                    float xv = xrow[k];
                    acc[i][0] = fmaf(xv, ws[k * OUT_F + lane], acc[i][0]);
                    acc[i][1] = fmaf(xv, ws[k * OUT_F + 32 + lane], acc[i][1]);
                }
            }
        }
    }

    if (node0 < n_nodes) {
        int nvalid = n_nodes - node0;
        if (nvalid > 8) nvalid = 8;
#pragma unroll
        for (int i = 0; i < 8; i++) {
            if (i < nvalid) {
                g_h[(size_t)(node0 + i) * OUT_F + lane]      = acc[i][0];
                g_h[(size_t)(node0 + i) * OUT_F + 32 + lane] = acc[i][1];
            }
        }
    }
}

// ---------------------------------------------------------------------------
// Init output to per-column bias (so edge atomics accumulate on top of it).
// ---------------------------------------------------------------------------
__global__ void init_kernel(float4* __restrict__ out4,
                            const float4* __restrict__ bias4, int total4) {
    int i = blockIdx.x * blockDim.x + threadIdx.x;
    if (i < total4) out4[i] = bias4[i & 15];   // OUT_F/4 = 16 float4 per row
}

// ---------------------------------------------------------------------------
// Edge scatter: 16 threads per edge, one float4 chunk each.
// out[dst] += h[src] * w  via no-return vector reduction (red.global.add.v4).
// ---------------------------------------------------------------------------
__device__ __forceinline__ void red_add_v4(float4* addr, float4 v) {
    asm volatile("red.global.add.v4.f32 [%0], {%1, %2, %3, %4};"
                 :: "l"(addr), "f"(v.x), "f"(v.y), "f"(v.z), "f"(v.w)
                 : "memory");
}

__global__ void edge_kernel(const unsigned int* __restrict__ src32,
                            const unsigned int* __restrict__ dst32,
                            const float* __restrict__ ew,
                            float4* __restrict__ out4,
                            int n_edges) {
    long long tid = (long long)blockIdx.x * blockDim.x + threadIdx.x;
    int e = (int)(tid >> 4);
    int c = (int)(tid & 15);
    if (e >= n_edges) return;

    int is64 = g_is64;
    unsigned int s, d;
    if (is64) { s = src32[2 * (size_t)e]; d = dst32[2 * (size_t)e]; }
    else      { s = src32[e];             d = dst32[e]; }

    float w = __ldg(&ew[e]);
    const float4* h4 = (const float4*)g_h;
    float4 v = h4[(size_t)s * 16 + c];
    float4 r = make_float4(v.x * w, v.y * w, v.z * w, v.w * w);
    red_add_v4(&out4[(size_t)d * 16 + c], r);
}

// ---------------------------------------------------------------------------
// Final ReLU sweep.
// ---------------------------------------------------------------------------
__global__ void relu_kernel(float4* __restrict__ out4, int total4) {
    int i = blockIdx.x * blockDim.x + threadIdx.x;
    if (i < total4) {
        float4 v = out4[i];
        v.x = fmaxf(v.x, 0.f);
        v.y = fmaxf(v.y, 0.f);
        v.z = fmaxf(v.z, 0.f);
        v.w = fmaxf(v.w, 0.f);
        out4[i] = v;
    }
}

// ---------------------------------------------------------------------------
extern "C" void kernel_launch(void* const* d_in, const int* in_sizes, int n_in,
                              void* d_out, int out_size) {
    const float*        x    = (const float*)d_in[0];
    const unsigned int* src  = (const unsigned int*)d_in[1];
    const unsigned int* dst  = (const unsigned int*)d_in[2];
    const float*        ew   = (const float*)d_in[3];
    const float*        w    = (const float*)d_in[4];
    const float*        bias = (const float*)d_in[5];
    float*              out  = (float*)d_out;

    int n_nodes = in_sizes[0] / IN_F;
    int n_edges = in_sizes[3];          // edge_weight count (dtype-independent)
    int total4  = n_nodes * (OUT_F / 4);

    // 0) index dtype detection
    detect_kernel<<<1, 32>>>(src, n_edges);

    // 1) h = x @ W   (64 nodes per block)
    int gemm_blocks = (n_nodes + 63) / 64;
    gemm_kernel<<<gemm_blocks, 256>>>(x, w, n_nodes);

    // 2) out = bias (broadcast)
    init_kernel<<<(total4 + 255) / 256, 256>>>((float4*)out, (const float4*)bias, total4);

    // 3) out[dst] += h[src] * ew
    long long work = (long long)n_edges * 16;
    int edge_blocks = (int)((work + 255) / 256);
    edge_kernel<<<edge_blocks, 256>>>(src, dst, ew, (float4*)out, n_edges);

    // 4) relu
    relu_kernel<<<(total4 + 255) / 256, 256>>>((float4*)out, total4);
}